// round 6
// baseline (speedup 1.0000x reference)
#include <cuda_runtime.h>
#include <cuda_bf16.h>
#include <cstdint>

#define B_  2
#define S_  2048
#define D_  1024
#define H_  16
#define HD_ 64
#define SCALE_ 0.125f
#define NTOK (B_*S_)   /* 4096 */

// ---------------- device scratch (allocation-free rule) ----------------
__device__ __nv_bfloat16 g_xh[NTOK*D_],  g_xl[NTOK*D_];
__device__ __nv_bfloat16 g_wqh[D_*3*D_], g_wql[D_*3*D_];
__device__ __nv_bfloat16 g_wph[D_*D_],   g_wpl[D_*D_];
__device__ __nv_bfloat16 g_Qh[NTOK*D_],  g_Ql[NTOK*D_];   // [B,H,S,HD], Q pre-scaled
__device__ __nv_bfloat16 g_Kh[NTOK*D_],  g_Kl[NTOK*D_];
__device__ __nv_bfloat16 g_Vh[NTOK*D_],  g_Vl[NTOK*D_];
__device__ __nv_bfloat16 g_ah[NTOK*D_],  g_al[NTOK*D_];   // attention out [4096,1024]

// ---------------- helpers ----------------
__device__ __forceinline__ unsigned smaddr(const void* p) {
    return (unsigned)__cvta_generic_to_shared(p);
}
__device__ __forceinline__ void ldsm4(unsigned r[4], unsigned a) {
    asm volatile("ldmatrix.sync.aligned.m8n8.x4.shared.b16 {%0,%1,%2,%3}, [%4];"
                 : "=r"(r[0]), "=r"(r[1]), "=r"(r[2]), "=r"(r[3]) : "r"(a));
}
__device__ __forceinline__ void ldsm4t(unsigned r[4], unsigned a) {
    asm volatile("ldmatrix.sync.aligned.m8n8.x4.trans.shared.b16 {%0,%1,%2,%3}, [%4];"
                 : "=r"(r[0]), "=r"(r[1]), "=r"(r[2]), "=r"(r[3]) : "r"(a));
}
__device__ __forceinline__ void mma_bf16(float c[4], const unsigned a[4],
                                         unsigned b0, unsigned b1) {
    asm volatile(
        "mma.sync.aligned.m16n8k16.row.col.f32.bf16.bf16.f32 "
        "{%0,%1,%2,%3},{%4,%5,%6,%7},{%8,%9},{%0,%1,%2,%3};"
        : "+f"(c[0]), "+f"(c[1]), "+f"(c[2]), "+f"(c[3])
        : "r"(a[0]), "r"(a[1]), "r"(a[2]), "r"(a[3]), "r"(b0), "r"(b1));
}
__device__ __forceinline__ void split2(float v0, float v1, unsigned& hp, unsigned& lp) {
    __nv_bfloat16 h0 = __float2bfloat16(v0), h1 = __float2bfloat16(v1);
    float r0 = v0 - __bfloat162float(h0), r1 = v1 - __bfloat162float(h1);
    __nv_bfloat162 hh = __halves2bfloat162(h0, h1);
    __nv_bfloat162 ll = __floats2bfloat162_rn(r0, r1);
    hp = *reinterpret_cast<unsigned*>(&hh);
    lp = *reinterpret_cast<unsigned*>(&ll);
}
__device__ __forceinline__ void cp16(uint32_t dst, const void* src) {
    asm volatile("cp.async.cg.shared.global [%0], [%1], 16;" :: "r"(dst), "l"(src) : "memory");
}
#define CP_COMMIT() asm volatile("cp.async.commit_group;" ::: "memory")
#define CP_WAIT1()  asm volatile("cp.async.wait_group 1;" ::: "memory")
#define CP_WAIT0()  asm volatile("cp.async.wait_group 0;" ::: "memory")

// ---------------- fused split-convert (x, Wqkv, Wproj in one launch) --------
#define N_X4  (NTOK*D_/4)
#define N_WQ4 (D_*3*D_/4)
#define N_WP4 (D_*D_/4)
__global__ void conv_all(const float* __restrict__ x,
                         const float* __restrict__ wq,
                         const float* __restrict__ wp) {
    size_t i = (size_t)blockIdx.x * 256 + threadIdx.x;
    const float* src; __nv_bfloat16 *h, *l; size_t j;
    if (i < N_X4)                { src = x;  h = g_xh;  l = g_xl;  j = i; }
    else if (i < N_X4 + N_WQ4)   { src = wq; h = g_wqh; l = g_wql; j = i - N_X4; }
    else                         { src = wp; h = g_wph; l = g_wpl; j = i - N_X4 - N_WQ4; }
    float4 v = ((const float4*)src)[j];
    unsigned h0, l0, h1, l1;
    split2(v.x, v.y, h0, l0);
    split2(v.z, v.w, h1, l1);
    *(unsigned*)(h + j * 4)     = h0;  *(unsigned*)(h + j * 4 + 2) = h1;
    *(unsigned*)(l + j * 4)     = l0;  *(unsigned*)(l + j * 4 + 2) = l1;
}

// ---------------- split-bf16 GEMM, cp.async 2-stage, 2 CTAs/SM ----------------
// stage layout (bytes): A0 @0 (10240), A1 @10240, B0 @20480 (8704), B1 @29184
#define GSS 37888
template <int GN, int MODE>
__global__ __launch_bounds__(256, 2) void gemm_cp(const float* __restrict__ bias,
                                                  float* __restrict__ outp) {
    extern __shared__ char smem[];
    const __nv_bfloat16* __restrict__ Ah = MODE ? g_ah : g_xh;
    const __nv_bfloat16* __restrict__ Al = MODE ? g_al : g_xl;
    const __nv_bfloat16* __restrict__ Bh = MODE ? g_wph : g_wqh;
    const __nv_bfloat16* __restrict__ Bl = MODE ? g_wpl : g_wql;

    const uint32_t sbase = smaddr(smem);
    const int tid = threadIdx.x, l = tid & 31, wid = tid >> 5;
    const int wm = (wid & 1) * 64, wn = (wid >> 1) * 32;
    const int rowBase = blockIdx.y * 128, colBase = blockIdx.x * 128;

    const int arow = tid >> 1, acol = (tid & 1) * 16;  // A: 128 rows x 32 k
    const int brow = tid >> 3, bcol = (tid & 7) * 16;  // B: 32 k x 128 n

    float c[4][4][4];
#pragma unroll
    for (int i = 0; i < 4; i++)
#pragma unroll
        for (int j = 0; j < 4; j++)
#pragma unroll
            for (int k = 0; k < 4; k++) c[i][j][k] = 0.f;

#define GEMM_LOAD(sb_, kt_) do {                                                   \
        const __nv_bfloat16* pa0 = Ah + (size_t)(rowBase + arow) * D_ + (kt_) * 32 + acol; \
        const __nv_bfloat16* pa1 = Al + (size_t)(rowBase + arow) * D_ + (kt_) * 32 + acol; \
        uint32_t da = (sb_) + (arow * 40 + acol) * 2;                              \
        cp16(da, pa0);               cp16(da + 16, pa0 + 8);                       \
        cp16(da + 10240, pa1);       cp16(da + 10240 + 16, pa1 + 8);               \
        const __nv_bfloat16* pb0 = Bh + (size_t)((kt_) * 32 + brow) * GN + colBase + bcol; \
        const __nv_bfloat16* pb1 = Bl + (size_t)((kt_) * 32 + brow) * GN + colBase + bcol; \
        uint32_t db = (sb_) + 20480 + (brow * 136 + bcol) * 2;                     \
        cp16(db, pb0);               cp16(db + 16, pb0 + 8);                       \
        cp16(db + 8704, pb1);        cp16(db + 8704 + 16, pb1 + 8);                \
    } while (0)

    GEMM_LOAD(sbase, 0);
    CP_COMMIT();

    const int nK = D_ / 32;
    for (int kt = 0; kt < nK; kt++) {
        if (kt + 1 < nK) {
            GEMM_LOAD(sbase + ((kt + 1) & 1) * GSS, kt + 1);
            CP_COMMIT();
            CP_WAIT1();
        } else {
            CP_WAIT0();
        }
        __syncthreads();
        const uint32_t sb = sbase + (kt & 1) * GSS;

#pragma unroll
        for (int k0 = 0; k0 < 32; k0 += 16) {
            unsigned ah[4][4], al[4][4];
            const int arow2 = wm + (l & 15);
            const int akc  = k0 + ((l >> 4) & 1) * 8;
#pragma unroll
            for (int mi = 0; mi < 4; mi++) {
                const uint32_t ao = ((arow2 + mi * 16) * 40 + akc) * 2;
                ldsm4(ah[mi], sb + ao);
                ldsm4(al[mi], sb + 10240 + ao);
            }
            const int brow2 = k0 + ((l >> 3) & 1) * 8 + (l & 7);
            const int bcol2 = wn + (l >> 4) * 8;
#pragma unroll
            for (int nj = 0; nj < 2; nj++) {
                unsigned bh4[4], bl4[4];
                const uint32_t bo = (brow2 * 136 + bcol2 + nj * 16) * 2;
                ldsm4t(bh4, sb + 20480 + bo);
                ldsm4t(bl4, sb + 29184 + bo);
#pragma unroll
                for (int mi = 0; mi < 4; mi++) mma_bf16(c[mi][2 * nj],     ah[mi], bh4[0], bh4[1]);
#pragma unroll
                for (int mi = 0; mi < 4; mi++) mma_bf16(c[mi][2 * nj + 1], ah[mi], bh4[2], bh4[3]);
#pragma unroll
                for (int mi = 0; mi < 4; mi++) mma_bf16(c[mi][2 * nj],     ah[mi], bl4[0], bl4[1]);
#pragma unroll
                for (int mi = 0; mi < 4; mi++) mma_bf16(c[mi][2 * nj + 1], ah[mi], bl4[2], bl4[3]);
#pragma unroll
                for (int mi = 0; mi < 4; mi++) mma_bf16(c[mi][2 * nj],     al[mi], bh4[0], bh4[1]);
#pragma unroll
                for (int mi = 0; mi < 4; mi++) mma_bf16(c[mi][2 * nj + 1], al[mi], bh4[2], bh4[3]);
            }
        }
        __syncthreads();
    }
#undef GEMM_LOAD

#pragma unroll
    for (int mi = 0; mi < 4; mi++) {
        const int r0 = rowBase + wm + mi * 16 + (l >> 2);
        const int r1 = r0 + 8;
#pragma unroll
        for (int g = 0; g < 4; g++) {
            const int nn = colBase + wn + g * 8 + 2 * (l & 3);
            if (MODE == 1) {
                float2 w;
                w.x = c[mi][g][0] + bias[nn];
                w.y = c[mi][g][1] + bias[nn + 1];
                *(float2*)(outp + (size_t)r0 * GN + nn) = w;
                w.x = c[mi][g][2] + bias[nn];
                w.y = c[mi][g][3] + bias[nn + 1];
                *(float2*)(outp + (size_t)r1 * GN + nn) = w;
            } else {
                const int which = nn >> 10, d = nn & 1023, hh = d >> 6, hd = d & 63;
                const float sc = (which == 0) ? SCALE_ : 1.f;
                __nv_bfloat16* dh = (which == 0) ? g_Qh : (which == 1) ? g_Kh : g_Vh;
                __nv_bfloat16* dl = (which == 0) ? g_Ql : (which == 1) ? g_Kl : g_Vl;
                const int b0i = r0 >> 11, s0i = r0 & 2047;
                const int b1i = r1 >> 11, s1i = r1 & 2047;
                const size_t i0 = (((size_t)(b0i * H_ + hh)) * S_ + s0i) * HD_ + hd;
                const size_t i1 = (((size_t)(b1i * H_ + hh)) * S_ + s1i) * HD_ + hd;
                unsigned hp, lp;
                split2((c[mi][g][0] + bias[nn]) * sc, (c[mi][g][1] + bias[nn + 1]) * sc, hp, lp);
                *(unsigned*)(dh + i0) = hp; *(unsigned*)(dl + i0) = lp;
                split2((c[mi][g][2] + bias[nn]) * sc, (c[mi][g][3] + bias[nn + 1]) * sc, hp, lp);
                *(unsigned*)(dh + i1) = hp; *(unsigned*)(dl + i1) = lp;
            }
        }
    }
}

// ---------------- flash attention, mma.sync + cp.async 2-stage ----------------
// stage layout (bytes): Ks0 @0, Ks1 @9216, Vs0 @18432, Vs1 @27648; stage = 36864
#define ASS 36864
__global__ __launch_bounds__(128) void attn_cp() {
    extern __shared__ char smem[];
    const uint32_t sbase = smaddr(smem);
    char* smemc = smem;
    const int qt = blockIdx.x, h = blockIdx.y, b = blockIdx.z;
    const int tid = threadIdx.x, l = tid & 31, wid = tid >> 5;

    const size_t headOff = ((size_t)(b * H_ + h)) * S_ * HD_;
    const __nv_bfloat16* Qh_g = g_Qh + headOff + (size_t)qt * 64 * HD_;
    const __nv_bfloat16* Ql_g = g_Ql + headOff + (size_t)qt * 64 * HD_;
    const __nv_bfloat16* Kh_g = g_Kh + headOff;
    const __nv_bfloat16* Kl_g = g_Kl + headOff;
    const __nv_bfloat16* Vh_g = g_Vh + headOff;
    const __nv_bfloat16* Vl_g = g_Vl + headOff;

    // stage Q through stage-0 K buffers, extract fragments
    for (int i = tid; i < 64 * 8; i += 128) {
        const int r = i >> 3, cc = (i & 7) * 8;
        *(uint4*)(smemc + (r * 72 + cc) * 2)        = *(const uint4*)(Qh_g + (size_t)r * HD_ + cc);
        *(uint4*)(smemc + 9216 + (r * 72 + cc) * 2) = *(const uint4*)(Ql_g + (size_t)r * HD_ + cc);
    }
    __syncthreads();
    unsigned qh[4][4], ql[4][4];
    {
        const int row = wid * 16 + (l & 15);
        const int kc  = ((l >> 4) & 1) * 8;
#pragma unroll
        for (int ks = 0; ks < 4; ks++) {
            const uint32_t qo = (row * 72 + ks * 16 + kc) * 2;
            ldsm4(qh[ks], sbase + qo);
            ldsm4(ql[ks], sbase + 9216 + qo);
        }
    }
    __syncthreads();

    float m0 = -1e30f, m1 = -1e30f, l0 = 0.f, l1 = 0.f;
    float o[8][4];
#pragma unroll
    for (int g = 0; g < 8; g++)
#pragma unroll
        for (int k = 0; k < 4; k++) o[g][k] = 0.f;

    const int lrow = tid >> 1, lcb = (tid & 1) * 32;
#define ATTN_LOAD(sb_, kt_) do {                                                  \
        const size_t ko = (size_t)(kt_) * 64 * HD_ + lrow * 64 + lcb;             \
        const __nv_bfloat16* pk0 = Kh_g + ko;                                     \
        const __nv_bfloat16* pk1 = Kl_g + ko;                                     \
        const __nv_bfloat16* pv0 = Vh_g + ko;                                     \
        const __nv_bfloat16* pv1 = Vl_g + ko;                                     \
        const uint32_t dd = (sb_) + (lrow * 72 + lcb) * 2;                        \
        _Pragma("unroll")                                                         \
        for (int q = 0; q < 4; q++) {                                             \
            cp16(dd + q * 16,         pk0 + q * 8);                               \
            cp16(dd + 9216 + q * 16,  pk1 + q * 8);                               \
            cp16(dd + 18432 + q * 16, pv0 + q * 8);                               \
            cp16(dd + 27648 + q * 16, pv1 + q * 8);                               \
        }                                                                         \
    } while (0)

    ATTN_LOAD(sbase, 0);
    CP_COMMIT();

    const int nKT = S_ / 64;
    for (int kt = 0; kt < nKT; kt++) {
        if (kt + 1 < nKT) {
            ATTN_LOAD(sbase + ((kt + 1) & 1) * ASS, kt + 1);
            CP_COMMIT();
            CP_WAIT1();
        } else {
            CP_WAIT0();
        }
        __syncthreads();
        const uint32_t sb = sbase + (kt & 1) * ASS;

        float sc[8][4];
#pragma unroll
        for (int g = 0; g < 8; g++)
#pragma unroll
            for (int k = 0; k < 4; k++) sc[g][k] = 0.f;

        const int rr = (l & 15);
#pragma unroll
        for (int ks = 0; ks < 4; ks++) {
            const int kc = ks * 16 + ((l >> 4) & 1) * 8;
            unsigned kh[4][4], kl[4][4];
#pragma unroll
            for (int kb = 0; kb < 4; kb++) {
                const uint32_t ko2 = ((kb * 16 + rr) * 72 + kc) * 2;
                ldsm4(kh[kb], sb + ko2);
                ldsm4(kl[kb], sb + 9216 + ko2);
            }
#pragma unroll
            for (int kb = 0; kb < 4; kb++) {
                mma_bf16(sc[2 * kb],     qh[ks], kh[kb][0], kh[kb][2]);
                mma_bf16(sc[2 * kb + 1], qh[ks], kh[kb][1], kh[kb][3]);
            }
#pragma unroll
            for (int kb = 0; kb < 4; kb++) {
                mma_bf16(sc[2 * kb],     qh[ks], kl[kb][0], kl[kb][2]);
                mma_bf16(sc[2 * kb + 1], qh[ks], kl[kb][1], kl[kb][3]);
            }
#pragma unroll
            for (int kb = 0; kb < 4; kb++) {
                mma_bf16(sc[2 * kb],     ql[ks], kh[kb][0], kh[kb][2]);
                mma_bf16(sc[2 * kb + 1], ql[ks], kh[kb][1], kh[kb][3]);
            }
        }

        // online softmax (rows l>>2 and +8)
        float mx0 = -1e30f, mx1 = -1e30f;
#pragma unroll
        for (int g = 0; g < 8; g++) {
            mx0 = fmaxf(mx0, fmaxf(sc[g][0], sc[g][1]));
            mx1 = fmaxf(mx1, fmaxf(sc[g][2], sc[g][3]));
        }
        mx0 = fmaxf(mx0, __shfl_xor_sync(0xffffffffu, mx0, 1));
        mx0 = fmaxf(mx0, __shfl_xor_sync(0xffffffffu, mx0, 2));
        mx1 = fmaxf(mx1, __shfl_xor_sync(0xffffffffu, mx1, 1));
        mx1 = fmaxf(mx1, __shfl_xor_sync(0xffffffffu, mx1, 2));
        const float mn0 = fmaxf(m0, mx0), mn1 = fmaxf(m1, mx1);
        const float al0 = __expf(m0 - mn0), al1 = __expf(m1 - mn1);
        m0 = mn0; m1 = mn1;
        float s0 = 0.f, s1 = 0.f;
#pragma unroll
        for (int g = 0; g < 8; g++) {
            sc[g][0] = __expf(sc[g][0] - mn0); s0 += sc[g][0];
            sc[g][1] = __expf(sc[g][1] - mn0); s0 += sc[g][1];
            sc[g][2] = __expf(sc[g][2] - mn1); s1 += sc[g][2];
            sc[g][3] = __expf(sc[g][3] - mn1); s1 += sc[g][3];
        }
        s0 += __shfl_xor_sync(0xffffffffu, s0, 1);
        s0 += __shfl_xor_sync(0xffffffffu, s0, 2);
        s1 += __shfl_xor_sync(0xffffffffu, s1, 1);
        s1 += __shfl_xor_sync(0xffffffffu, s1, 2);
        l0 = l0 * al0 + s0;
        l1 = l1 * al1 + s1;
#pragma unroll
        for (int g = 0; g < 8; g++) {
            o[g][0] *= al0; o[g][1] *= al0;
            o[g][2] *= al1; o[g][3] *= al1;
        }

        // PV
#pragma unroll
        for (int j = 0; j < 4; j++) {
            unsigned ph[4], pl[4];
            split2(sc[2 * j][0],     sc[2 * j][1],     ph[0], pl[0]);
            split2(sc[2 * j][2],     sc[2 * j][3],     ph[1], pl[1]);
            split2(sc[2 * j + 1][0], sc[2 * j + 1][1], ph[2], pl[2]);
            split2(sc[2 * j + 1][2], sc[2 * j + 1][3], ph[3], pl[3]);
            const int rr2 = 16 * j + ((l >> 3) & 1) * 8 + (l & 7);
            const int cc2 = ((l >> 4) & 1) * 8;
            unsigned vh[4][4], vl[4][4];
#pragma unroll
            for (int nb = 0; nb < 4; nb++) {
                const uint32_t vo = (rr2 * 72 + nb * 16 + cc2) * 2;
                ldsm4t(vh[nb], sb + 18432 + vo);
                ldsm4t(vl[nb], sb + 27648 + vo);
            }
#pragma unroll
            for (int nb = 0; nb < 4; nb++) {
                mma_bf16(o[2 * nb],     ph, vh[nb][0], vh[nb][1]);
                mma_bf16(o[2 * nb + 1], ph, vh[nb][2], vh[nb][3]);
            }
#pragma unroll
            for (int nb = 0; nb < 4; nb++) {
                mma_bf16(o[2 * nb],     ph, vl[nb][0], vl[nb][1]);
                mma_bf16(o[2 * nb + 1], ph, vl[nb][2], vl[nb][3]);
            }
#pragma unroll
            for (int nb = 0; nb < 4; nb++) {
                mma_bf16(o[2 * nb],     pl, vh[nb][0], vh[nb][1]);
                mma_bf16(o[2 * nb + 1], pl, vh[nb][2], vh[nb][3]);
            }
        }
        __syncthreads();
    }
#undef ATTN_LOAD

    const float inv0 = 1.f / l0, inv1 = 1.f / l1;
    const int r0 = qt * 64 + wid * 16 + (l >> 2);
    const int r1 = r0 + 8;
#pragma unroll
    for (int g = 0; g < 8; g++) {
        const int col = h * 64 + g * 8 + 2 * (l & 3);
        unsigned hp, lp;
        split2(o[g][0] * inv0, o[g][1] * inv0, hp, lp);
        *(unsigned*)&g_ah[(size_t)(b * S_ + r0) * D_ + col] = hp;
        *(unsigned*)&g_al[(size_t)(b * S_ + r0) * D_ + col] = lp;
        split2(o[g][2] * inv1, o[g][3] * inv1, hp, lp);
        *(unsigned*)&g_ah[(size_t)(b * S_ + r1) * D_ + col] = hp;
        *(unsigned*)&g_al[(size_t)(b * S_ + r1) * D_ + col] = lp;
    }
}

// ---------------------------------------------------------------------------
extern "C" void kernel_launch(void* const* d_in, const int* in_sizes, int n_in,
                              void* d_out, int out_size) {
    const float* x     = (const float*)d_in[0];
    const float* Wqkv  = (const float*)d_in[1];
    const float* bqkv  = (const float*)d_in[2];
    const float* Wproj = (const float*)d_in[3];
    const float* bproj = (const float*)d_in[4];
    float* out = (float*)d_out;

    cudaFuncSetAttribute(gemm_cp<3 * D_, 0>,
                         cudaFuncAttributeMaxDynamicSharedMemorySize, 2 * GSS);
    cudaFuncSetAttribute(gemm_cp<D_, 1>,
                         cudaFuncAttributeMaxDynamicSharedMemorySize, 2 * GSS);
    cudaFuncSetAttribute(attn_cp,
                         cudaFuncAttributeMaxDynamicSharedMemorySize, 2 * ASS);

    conv_all<<<(N_X4 + N_WQ4 + N_WP4) / 256, 256>>>(x, Wqkv, Wproj);

    dim3 g1(3 * D_ / 128, NTOK / 128);              // 24 x 32
    gemm_cp<3 * D_, 0><<<g1, 256, 2 * GSS>>>(bqkv, nullptr);

    dim3 g2(S_ / 64, H_, B_);                       // 32 x 16 x 2
    attn_cp<<<g2, 128, 2 * ASS>>>();

    dim3 g3(D_ / 128, NTOK / 128);                  // 8 x 32
    gemm_cp<D_, 1><<<g3, 256, 2 * GSS>>>(bproj, out);
}

// round 8
// speedup vs baseline: 2.4079x; 2.4079x over previous
#include <cuda_runtime.h>
#include <cuda_fp16.h>
#include <cstdint>

#define B_  2
#define S_  2048
#define D_  1024
#define H_  16
#define HD_ 64
#define SCALE_ 0.125f
#define NTOK (B_*S_)   /* 4096 */

// ---------------- device scratch (allocation-free rule) ----------------
__device__ __half g_xh[NTOK*D_],  g_xl[NTOK*D_];   // x split
__device__ __half g_wqh[D_*3*D_];                  // Wqkv hi only
__device__ __half g_wph[D_*D_];                    // Wproj hi only
__device__ __half g_Qh[NTOK*D_],  g_Ql[NTOK*D_];   // Q split, pre-scaled, [B,H,S,HD]
__device__ __half g_Kh[NTOK*D_];                   // K hi only
__device__ __half g_Vh[NTOK*D_];                   // V hi only
__device__ __half g_ah[NTOK*D_],  g_al[NTOK*D_];   // attention out split [4096,1024]

// ---------------- helpers ----------------
__device__ __forceinline__ unsigned smaddr(const void* p) {
    return (unsigned)__cvta_generic_to_shared(p);
}
__device__ __forceinline__ void ldsm4(unsigned r[4], unsigned a) {
    asm volatile("ldmatrix.sync.aligned.m8n8.x4.shared.b16 {%0,%1,%2,%3}, [%4];"
                 : "=r"(r[0]), "=r"(r[1]), "=r"(r[2]), "=r"(r[3]) : "r"(a));
}
__device__ __forceinline__ void ldsm4t(unsigned r[4], unsigned a) {
    asm volatile("ldmatrix.sync.aligned.m8n8.x4.trans.shared.b16 {%0,%1,%2,%3}, [%4];"
                 : "=r"(r[0]), "=r"(r[1]), "=r"(r[2]), "=r"(r[3]) : "r"(a));
}
__device__ __forceinline__ void mma_f16(float c[4], const unsigned a[4],
                                        unsigned b0, unsigned b1) {
    asm volatile(
        "mma.sync.aligned.m16n8k16.row.col.f32.f16.f16.f32 "
        "{%0,%1,%2,%3},{%4,%5,%6,%7},{%8,%9},{%0,%1,%2,%3};"
        : "+f"(c[0]), "+f"(c[1]), "+f"(c[2]), "+f"(c[3])
        : "r"(a[0]), "r"(a[1]), "r"(a[2]), "r"(a[3]), "r"(b0), "r"(b1));
}
// split two fp32 into packed-fp16 hi pair + lo pair
__device__ __forceinline__ void split2h(float v0, float v1, unsigned& hp, unsigned& lp) {
    __half h0 = __float2half(v0), h1 = __float2half(v1);
    float r0 = v0 - __half2float(h0), r1 = v1 - __half2float(h1);
    __half2 hh = __halves2half2(h0, h1);
    __half2 ll = __floats2half2_rn(r0, r1);
    hp = *reinterpret_cast<unsigned*>(&hh);
    lp = *reinterpret_cast<unsigned*>(&ll);
}
__device__ __forceinline__ unsigned packh(float v0, float v1) {
    __half2 hh = __floats2half2_rn(v0, v1);
    return *reinterpret_cast<unsigned*>(&hh);
}

// ---------------- fused conversion (x split; weights hi-only) ----------------
#define N_X4  (NTOK*D_/4)
#define N_WQ4 (D_*3*D_/4)
#define N_WP4 (D_*D_/4)
__global__ void conv_all(const float* __restrict__ x,
                         const float* __restrict__ wq,
                         const float* __restrict__ wp) {
    size_t i = (size_t)blockIdx.x * 256 + threadIdx.x;
    if (i < N_X4) {
        float4 v = ((const float4*)x)[i];
        unsigned h0, l0, h1, l1;
        split2h(v.x, v.y, h0, l0);
        split2h(v.z, v.w, h1, l1);
        *(unsigned*)(g_xh + i * 4)     = h0;  *(unsigned*)(g_xh + i * 4 + 2) = h1;
        *(unsigned*)(g_xl + i * 4)     = l0;  *(unsigned*)(g_xl + i * 4 + 2) = l1;
    } else if (i < N_X4 + N_WQ4) {
        size_t j = i - N_X4;
        float4 v = ((const float4*)wq)[j];
        *(unsigned*)(g_wqh + j * 4)     = packh(v.x, v.y);
        *(unsigned*)(g_wqh + j * 4 + 2) = packh(v.z, v.w);
    } else {
        size_t j = i - N_X4 - N_WQ4;
        float4 v = ((const float4*)wp)[j];
        *(unsigned*)(g_wph + j * 4)     = packh(v.x, v.y);
        *(unsigned*)(g_wph + j * 4 + 2) = packh(v.z, v.w);
    }
}

// ---------------- fp16 2-term GEMM (128x128 tile, BK=32, 8 warps) -------------
// C = (Ah + Al) x Bh.   MODE 0: QKV epilogue; MODE 1: proj epilogue.
template <int GN, int MODE>
__global__ __launch_bounds__(256) void gemm_split(const float* __restrict__ bias,
                                                  float* __restrict__ outp) {
    const __half* __restrict__ Ah = MODE ? g_ah : g_xh;
    const __half* __restrict__ Al = MODE ? g_al : g_xl;
    const __half* __restrict__ Bh = MODE ? g_wph : g_wqh;

    __shared__ __half As0[128 * 40], As1[128 * 40];   // rows padded to 40
    __shared__ __half Bs[32 * 136];                   // rows padded to 136

    const int tid = threadIdx.x, l = tid & 31, wid = tid >> 5;
    const int wm = (wid & 1) * 64, wn = (wid >> 1) * 32;
    const int rowBase = blockIdx.y * 128, colBase = blockIdx.x * 128;

    const int ar = tid >> 2,  ac = (tid & 3) * 8;
    const int br = tid >> 4,  bc = (tid & 15) * 8;

    const __half* gA0 = Ah + (size_t)(rowBase + ar) * D_ + ac;
    const __half* gA1 = Al + (size_t)(rowBase + ar) * D_ + ac;
    const __half* gB0 = Bh + (size_t)br * GN + colBase + bc;

    float c[4][4][4];
#pragma unroll
    for (int i = 0; i < 4; i++)
#pragma unroll
        for (int j = 0; j < 4; j++)
#pragma unroll
            for (int k = 0; k < 4; k++) c[i][j][k] = 0.f;

    *(uint4*)&As0[ar * 40 + ac]        = *(const uint4*)(gA0);
    *(uint4*)&As0[(ar + 64) * 40 + ac] = *(const uint4*)(gA0 + (size_t)64 * D_);
    *(uint4*)&As1[ar * 40 + ac]        = *(const uint4*)(gA1);
    *(uint4*)&As1[(ar + 64) * 40 + ac] = *(const uint4*)(gA1 + (size_t)64 * D_);
    *(uint4*)&Bs[br * 136 + bc]        = *(const uint4*)(gB0);
    *(uint4*)&Bs[(br + 16) * 136 + bc] = *(const uint4*)(gB0 + (size_t)16 * GN);
    __syncthreads();

    const int nK = D_ / 32;
    for (int kt = 0; kt < nK; kt++) {
        uint4 pa0a, pa0b, pa1a, pa1b, pb0a, pb0b;
        if (kt + 1 < nK) {
            const size_t aoff = (size_t)(kt + 1) * 32;
            pa0a = *(const uint4*)(gA0 + aoff);
            pa0b = *(const uint4*)(gA0 + aoff + (size_t)64 * D_);
            pa1a = *(const uint4*)(gA1 + aoff);
            pa1b = *(const uint4*)(gA1 + aoff + (size_t)64 * D_);
            const size_t boff = (size_t)(kt + 1) * 32 * GN;
            pb0a = *(const uint4*)(gB0 + boff);
            pb0b = *(const uint4*)(gB0 + boff + (size_t)16 * GN);
        }

#pragma unroll
        for (int k0 = 0; k0 < 32; k0 += 16) {
            unsigned ah[4][4], al[4][4];
            const int arow = wm + (l & 15);
            const int akc  = k0 + ((l >> 4) & 1) * 8;
#pragma unroll
            for (int mi = 0; mi < 4; mi++) {
                ldsm4(ah[mi], smaddr(&As0[(arow + mi * 16) * 40 + akc]));
                ldsm4(al[mi], smaddr(&As1[(arow + mi * 16) * 40 + akc]));
            }
            const int brow = k0 + ((l >> 3) & 1) * 8 + (l & 7);
            const int bcol = wn + (l >> 4) * 8;
#pragma unroll
            for (int nj = 0; nj < 2; nj++) {
                unsigned bh4[4];
                ldsm4t(bh4, smaddr(&Bs[brow * 136 + bcol + nj * 16]));
#pragma unroll
                for (int mi = 0; mi < 4; mi++) mma_f16(c[mi][2 * nj],     ah[mi], bh4[0], bh4[1]);
#pragma unroll
                for (int mi = 0; mi < 4; mi++) mma_f16(c[mi][2 * nj + 1], ah[mi], bh4[2], bh4[3]);
#pragma unroll
                for (int mi = 0; mi < 4; mi++) mma_f16(c[mi][2 * nj],     al[mi], bh4[0], bh4[1]);
#pragma unroll
                for (int mi = 0; mi < 4; mi++) mma_f16(c[mi][2 * nj + 1], al[mi], bh4[2], bh4[3]);
            }
        }

        if (kt + 1 < nK) {
            __syncthreads();
            *(uint4*)&As0[ar * 40 + ac]         = pa0a;
            *(uint4*)&As0[(ar + 64) * 40 + ac]  = pa0b;
            *(uint4*)&As1[ar * 40 + ac]         = pa1a;
            *(uint4*)&As1[(ar + 64) * 40 + ac]  = pa1b;
            *(uint4*)&Bs[br * 136 + bc]         = pb0a;
            *(uint4*)&Bs[(br + 16) * 136 + bc]  = pb0b;
            __syncthreads();
        }
    }

#pragma unroll
    for (int mi = 0; mi < 4; mi++) {
        const int r0 = rowBase + wm + mi * 16 + (l >> 2);
        const int r1 = r0 + 8;
#pragma unroll
        for (int g = 0; g < 4; g++) {
            const int nn = colBase + wn + g * 8 + 2 * (l & 3);
            if (MODE == 1) {
                float2 w;
                w.x = c[mi][g][0] + bias[nn];
                w.y = c[mi][g][1] + bias[nn + 1];
                *(float2*)(outp + (size_t)r0 * GN + nn) = w;
                w.x = c[mi][g][2] + bias[nn];
                w.y = c[mi][g][3] + bias[nn + 1];
                *(float2*)(outp + (size_t)r1 * GN + nn) = w;
            } else {
                const int which = nn >> 10, d = nn & 1023, hh = d >> 6, hd = d & 63;
                const int b0i = r0 >> 11, s0i = r0 & 2047;
                const int b1i = r1 >> 11, s1i = r1 & 2047;
                const size_t i0 = (((size_t)(b0i * H_ + hh)) * S_ + s0i) * HD_ + hd;
                const size_t i1 = (((size_t)(b1i * H_ + hh)) * S_ + s1i) * HD_ + hd;
                const float v00 = c[mi][g][0] + bias[nn];
                const float v01 = c[mi][g][1] + bias[nn + 1];
                const float v10 = c[mi][g][2] + bias[nn];
                const float v11 = c[mi][g][3] + bias[nn + 1];
                if (which == 0) {          // Q: pre-scale + split
                    unsigned hp, lp;
                    split2h(v00 * SCALE_, v01 * SCALE_, hp, lp);
                    *(unsigned*)(g_Qh + i0) = hp; *(unsigned*)(g_Ql + i0) = lp;
                    split2h(v10 * SCALE_, v11 * SCALE_, hp, lp);
                    *(unsigned*)(g_Qh + i1) = hp; *(unsigned*)(g_Ql + i1) = lp;
                } else {                   // K or V: hi only
                    __half* dst = (which == 1) ? g_Kh : g_Vh;
                    *(unsigned*)(dst + i0) = packh(v00, v01);
                    *(unsigned*)(dst + i1) = packh(v10, v11);
                }
            }
        }
    }
}

// ---------------- flash attention, fp16 2-term mma.sync ----------------------
__global__ __launch_bounds__(128) void attn_mma() {
    const int qt = blockIdx.x, h = blockIdx.y, b = blockIdx.z;
    const int tid = threadIdx.x, l = tid & 31, wid = tid >> 5;

    __shared__ __half Ks[64 * 72];   // K hi tile (also Q-hi staging)
    __shared__ __half Vs[64 * 72];   // V hi tile (also Q-lo staging)

    const size_t headOff = ((size_t)(b * H_ + h)) * S_ * HD_;
    const __half* Qh_g = g_Qh + headOff + (size_t)qt * 64 * HD_;
    const __half* Ql_g = g_Ql + headOff + (size_t)qt * 64 * HD_;
    const __half* Kh_g = g_Kh + headOff;
    const __half* Vh_g = g_Vh + headOff;

    // stage Q (hi in Ks, lo in Vs), extract fragments
    for (int i = tid; i < 64 * 8; i += 128) {
        const int r = i >> 3, cc = (i & 7) * 8;
        *(uint4*)&Ks[r * 72 + cc] = *(const uint4*)(Qh_g + (size_t)r * HD_ + cc);
        *(uint4*)&Vs[r * 72 + cc] = *(const uint4*)(Ql_g + (size_t)r * HD_ + cc);
    }
    __syncthreads();
    unsigned qh[4][4], ql[4][4];
    {
        const int row = wid * 16 + (l & 15);
        const int kc  = ((l >> 4) & 1) * 8;
#pragma unroll
        for (int ks = 0; ks < 4; ks++) {
            ldsm4(qh[ks], smaddr(&Ks[row * 72 + ks * 16 + kc]));
            ldsm4(ql[ks], smaddr(&Vs[row * 72 + ks * 16 + kc]));
        }
    }
    __syncthreads();

    float m0 = -1e30f, m1 = -1e30f, l0 = 0.f, l1 = 0.f;
    float o[8][4];
#pragma unroll
    for (int g = 0; g < 8; g++)
#pragma unroll
        for (int k = 0; k < 4; k++) o[g][k] = 0.f;

    for (int kt = 0; kt < S_ / 64; kt++) {
        const size_t koff = (size_t)kt * 64 * HD_;
        for (int i = tid; i < 64 * 8; i += 128) {
            const int r = i >> 3, cc = (i & 7) * 8;
            const size_t src = koff + (size_t)r * HD_ + cc;
            *(uint4*)&Ks[r * 72 + cc] = *(const uint4*)(Kh_g + src);
            *(uint4*)&Vs[r * 72 + cc] = *(const uint4*)(Vh_g + src);
        }
        __syncthreads();

        // scores = (Qh + Ql) x Kh
        float sc[8][4];
#pragma unroll
        for (int g = 0; g < 8; g++)
#pragma unroll
            for (int k = 0; k < 4; k++) sc[g][k] = 0.f;

        const int rr = (l & 15);
#pragma unroll
        for (int ks = 0; ks < 4; ks++) {
            const int kc = ks * 16 + ((l >> 4) & 1) * 8;
            unsigned kh[4][4];
#pragma unroll
            for (int kb = 0; kb < 4; kb++)
                ldsm4(kh[kb], smaddr(&Ks[(kb * 16 + rr) * 72 + kc]));
#pragma unroll
            for (int kb = 0; kb < 4; kb++) {
                mma_f16(sc[2 * kb],     qh[ks], kh[kb][0], kh[kb][2]);
                mma_f16(sc[2 * kb + 1], qh[ks], kh[kb][1], kh[kb][3]);
            }
#pragma unroll
            for (int kb = 0; kb < 4; kb++) {
                mma_f16(sc[2 * kb],     ql[ks], kh[kb][0], kh[kb][2]);
                mma_f16(sc[2 * kb + 1], ql[ks], kh[kb][1], kh[kb][3]);
            }
        }

        // online softmax (rows l>>2 and +8)
        float mx0 = -1e30f, mx1 = -1e30f;
#pragma unroll
        for (int g = 0; g < 8; g++) {
            mx0 = fmaxf(mx0, fmaxf(sc[g][0], sc[g][1]));
            mx1 = fmaxf(mx1, fmaxf(sc[g][2], sc[g][3]));
        }
        mx0 = fmaxf(mx0, __shfl_xor_sync(0xffffffffu, mx0, 1));
        mx0 = fmaxf(mx0, __shfl_xor_sync(0xffffffffu, mx0, 2));
        mx1 = fmaxf(mx1, __shfl_xor_sync(0xffffffffu, mx1, 1));
        mx1 = fmaxf(mx1, __shfl_xor_sync(0xffffffffu, mx1, 2));
        const float mn0 = fmaxf(m0, mx0), mn1 = fmaxf(m1, mx1);
        const float al0 = __expf(m0 - mn0), al1 = __expf(m1 - mn1);
        m0 = mn0; m1 = mn1;
        float s0 = 0.f, s1 = 0.f;
#pragma unroll
        for (int g = 0; g < 8; g++) {
            sc[g][0] = __expf(sc[g][0] - mn0); s0 += sc[g][0];
            sc[g][1] = __expf(sc[g][1] - mn0); s0 += sc[g][1];
            sc[g][2] = __expf(sc[g][2] - mn1); s1 += sc[g][2];
            sc[g][3] = __expf(sc[g][3] - mn1); s1 += sc[g][3];
        }
        s0 += __shfl_xor_sync(0xffffffffu, s0, 1);
        s0 += __shfl_xor_sync(0xffffffffu, s0, 2);
        s1 += __shfl_xor_sync(0xffffffffu, s1, 1);
        s1 += __shfl_xor_sync(0xffffffffu, s1, 2);
        l0 = l0 * al0 + s0;
        l1 = l1 * al1 + s1;
#pragma unroll
        for (int g = 0; g < 8; g++) {
            o[g][0] *= al0; o[g][1] *= al0;
            o[g][2] *= al1; o[g][3] *= al1;
        }

        // PV = (Ph + Pl) x Vh
#pragma unroll
        for (int j = 0; j < 4; j++) {
            unsigned ph[4], pl[4];
            split2h(sc[2 * j][0],     sc[2 * j][1],     ph[0], pl[0]);
            split2h(sc[2 * j][2],     sc[2 * j][3],     ph[1], pl[1]);
            split2h(sc[2 * j + 1][0], sc[2 * j + 1][1], ph[2], pl[2]);
            split2h(sc[2 * j + 1][2], sc[2 * j + 1][3], ph[3], pl[3]);
            const int rr2 = 16 * j + ((l >> 3) & 1) * 8 + (l & 7);
            const int cc2 = ((l >> 4) & 1) * 8;
            unsigned vh[4][4];
#pragma unroll
            for (int nb = 0; nb < 4; nb++)
                ldsm4t(vh[nb], smaddr(&Vs[rr2 * 72 + nb * 16 + cc2]));
#pragma unroll
            for (int nb = 0; nb < 4; nb++) {
                mma_f16(o[2 * nb],     ph, vh[nb][0], vh[nb][1]);
                mma_f16(o[2 * nb + 1], ph, vh[nb][2], vh[nb][3]);
            }
#pragma unroll
            for (int nb = 0; nb < 4; nb++) {
                mma_f16(o[2 * nb],     pl, vh[nb][0], vh[nb][1]);
                mma_f16(o[2 * nb + 1], pl, vh[nb][2], vh[nb][3]);
            }
        }
        __syncthreads();
    }

    // epilogue: normalize, split fp16, store g_a
    const float inv0 = 1.f / l0, inv1 = 1.f / l1;
    const int r0 = qt * 64 + wid * 16 + (l >> 2);
    const int r1 = r0 + 8;
#pragma unroll
    for (int g = 0; g < 8; g++) {
        const int col = h * 64 + g * 8 + 2 * (l & 3);
        unsigned hp, lp;
        split2h(o[g][0] * inv0, o[g][1] * inv0, hp, lp);
        *(unsigned*)&g_ah[(size_t)(b * S_ + r0) * D_ + col] = hp;
        *(unsigned*)&g_al[(size_t)(b * S_ + r0) * D_ + col] = lp;
        split2h(o[g][2] * inv1, o[g][3] * inv1, hp, lp);
        *(unsigned*)&g_ah[(size_t)(b * S_ + r1) * D_ + col] = hp;
        *(unsigned*)&g_al[(size_t)(b * S_ + r1) * D_ + col] = lp;
    }
}

// ---------------------------------------------------------------------------
extern "C" void kernel_launch(void* const* d_in, const int* in_sizes, int n_in,
                              void* d_out, int out_size) {
    const float* x     = (const float*)d_in[0];
    const float* Wqkv  = (const float*)d_in[1];
    const float* bqkv  = (const float*)d_in[2];
    const float* Wproj = (const float*)d_in[3];
    const float* bproj = (const float*)d_in[4];
    float* out = (float*)d_out;

    conv_all<<<(N_X4 + N_WQ4 + N_WP4) / 256, 256>>>(x, Wqkv, Wproj);

    dim3 g1(3 * D_ / 128, NTOK / 128);              // 24 x 32
    gemm_split<3 * D_, 0><<<g1, 256>>>(bqkv, nullptr);

    dim3 g2(S_ / 64, H_, B_);                       // 32 x 16 x 2
    attn_mma<<<g2, 128>>>();

    dim3 g3(D_ / 128, NTOK / 128);                  // 8 x 32
    gemm_split<D_, 1><<<g3, 256>>>(bproj, out);
}